// round 2
// baseline (speedup 1.0000x reference)
#include <cuda_runtime.h>
#include <math.h>

#define NE 8
#define NT 4096
#define ND 1024
#define NH 4096
#define SLOTS (2*NT + 64)

// ---------------- scratch (device globals; no allocation allowed) -----------
__device__ int   g_topi[NT*2];
__device__ float g_topw[NT*2];
__device__ int   g_cnt[NE];
__device__ float g_psum[NE];
__device__ int   g_off[NE+1];
__device__ int   g_cur[NE];
__device__ int   g_list[SLOTS];
__device__ int   g_slot[NT*2];
__device__ float g_H[(size_t)SLOTS*NH];   // ~135 MB
__device__ float g_Y[(size_t)SLOTS*ND];   // ~34 MB

// ---------------- init: reset per-launch counters ---------------------------
__global__ void k_init() {
    int i = threadIdx.x;
    if (i < NE) { g_cnt[i] = 0; g_psum[i] = 0.f; g_cur[i] = 0; }
}

// ---------------- router: logits, softmax, top-2, aux accumulators ----------
__global__ __launch_bounds__(256) void k_router(const float* __restrict__ x,
                                                const float* __restrict__ Wg) {
    __shared__ float sW[NE * ND];     // 32 KB
    int tid = threadIdx.x;
    for (int i = tid; i < NE * ND; i += 256) sW[i] = Wg[i];
    __syncthreads();

    int warp = tid >> 5, lane = tid & 31;
    int t = blockIdx.x * 8 + warp;

    float acc[NE];
#pragma unroll
    for (int e = 0; e < NE; e++) acc[e] = 0.f;
    const float* xr = x + (size_t)t * ND;
    for (int d = lane; d < ND; d += 32) {
        float xv = xr[d];
#pragma unroll
        for (int e = 0; e < NE; e++) acc[e] = fmaf(xv, sW[e * ND + d], acc[e]);
    }
#pragma unroll
    for (int e = 0; e < NE; e++) {
#pragma unroll
        for (int off = 16; off; off >>= 1)
            acc[e] += __shfl_xor_sync(0xffffffffu, acc[e], off);
    }

    if (lane == 0) {
        float mx = acc[0];
#pragma unroll
        for (int e = 1; e < NE; e++) mx = fmaxf(mx, acc[e]);
        float p[NE], Z = 0.f;
#pragma unroll
        for (int e = 0; e < NE; e++) { p[e] = expf(acc[e] - mx); Z += p[e]; }
        float inv = 1.f / Z;
#pragma unroll
        for (int e = 0; e < NE; e++) { p[e] *= inv; atomicAdd(&g_psum[e], p[e]); }

        // top-2, lowest-index tie-break (matches jax.lax.top_k)
        int i0 = 0;
#pragma unroll
        for (int e = 1; e < NE; e++) if (p[e] > p[i0]) i0 = e;
        int i1 = (i0 == 0) ? 1 : 0;
#pragma unroll
        for (int e = 0; e < NE; e++) if (e != i0 && p[e] > p[i1]) i1 = e;

        float s = p[i0] + p[i1];
        g_topi[t * 2 + 0] = i0;  g_topi[t * 2 + 1] = i1;
        g_topw[t * 2 + 0] = p[i0] / s;  g_topw[t * 2 + 1] = p[i1] / s;
        atomicAdd(&g_cnt[i0], 1);
        atomicAdd(&g_cnt[i1], 1);
    }
}

// ---------------- scan: offsets + aux loss ----------------------------------
__global__ void k_scan(float* __restrict__ out, int out_size) {
    if (threadIdx.x == 0 && blockIdx.x == 0) {
        int off = 0;
        for (int e = 0; e < NE; e++) { g_off[e] = off; off += g_cnt[e]; }
        g_off[NE] = off;
        float invT = 1.f / (float)NT;
        float aux = 0.f;
        for (int e = 0; e < NE; e++)
            aux += ((float)g_cnt[e] * invT) * (g_psum[e] * invT);
        aux *= (float)NE;
        if (out_size > NT * ND) out[(size_t)NT * ND] = aux;
    }
}

// ---------------- fill: scatter tokens into compact per-expert slot lists ---
__global__ void k_fill() {
    int t = blockIdx.x * blockDim.x + threadIdx.x;
    if (t >= NT) return;
#pragma unroll
    for (int k = 0; k < 2; k++) {
        int e = g_topi[t * 2 + k];
        int pos = atomicAdd(&g_cur[e], 1);
        int s = g_off[e] + pos;
        g_list[s] = t;
        g_slot[t * 2 + k] = s;
    }
}

// ---------------- GEMM1: H = silu(gather(x) @ W1[e] + b1[e]) ----------------
__global__ __launch_bounds__(256) void k_gemm1(const float* __restrict__ x,
                                               const float* __restrict__ W1,
                                               const float* __restrict__ b1) {
    int e = blockIdx.z;
    int ne = g_cnt[e];
    int mt = blockIdx.x;
    if (mt * 64 >= ne) return;
    int row0  = g_off[e] + mt * 64;
    int valid = ne - mt * 64; if (valid > 64) valid = 64;
    int n0 = blockIdx.y * 64;

    __shared__ float As[16][64];
    __shared__ float Bs[16][64];

    int tid = threadIdx.x;
    int lm = tid >> 2, lk = (tid & 3) * 4;     // A-tile loader: row, k-quad
    int bk = tid >> 4, bn = (tid & 15) * 4;    // B-tile loader
    int ty = (tid >> 4) * 4, tx = (tid & 15) * 4;

    const float* W1e = W1 + (size_t)e * ND * NH;
    long xoff = -1;
    if (lm < valid) xoff = (long)g_list[row0 + lm] * ND + lk;

    float acc[4][4];
#pragma unroll
    for (int i = 0; i < 4; i++)
#pragma unroll
        for (int j = 0; j < 4; j++) acc[i][j] = 0.f;

    for (int k0 = 0; k0 < ND; k0 += 16) {
        float4 av = make_float4(0.f, 0.f, 0.f, 0.f);
        if (xoff >= 0) av = *(const float4*)(x + xoff + k0);
        As[lk + 0][lm] = av.x; As[lk + 1][lm] = av.y;
        As[lk + 2][lm] = av.z; As[lk + 3][lm] = av.w;
        *(float4*)&Bs[bk][bn] =
            *(const float4*)(W1e + (size_t)(k0 + bk) * NH + n0 + bn);
        __syncthreads();
#pragma unroll
        for (int k = 0; k < 16; k++) {
            float4 a = *(const float4*)&As[k][ty];
            float4 b = *(const float4*)&Bs[k][tx];
            float a4[4] = {a.x, a.y, a.z, a.w};
            float b4[4] = {b.x, b.y, b.z, b.w};
#pragma unroll
            for (int i = 0; i < 4; i++)
#pragma unroll
                for (int j = 0; j < 4; j++)
                    acc[i][j] = fmaf(a4[i], b4[j], acc[i][j]);
        }
        __syncthreads();
    }

#pragma unroll
    for (int i = 0; i < 4; i++) {
        if (ty + i < valid) {
            size_t row = (size_t)(row0 + ty + i);
#pragma unroll
            for (int j = 0; j < 4; j++) {
                int col = n0 + tx + j;
                float z = acc[i][j] + b1[e * NH + col];
                g_H[row * NH + col] = z / (1.f + expf(-z));
            }
        }
    }
}

// ---------------- GEMM2: Y = H @ W2[e] + b2[e] -------------------------------
__global__ __launch_bounds__(256) void k_gemm2(const float* __restrict__ W2,
                                               const float* __restrict__ b2) {
    int e = blockIdx.z;
    int ne = g_cnt[e];
    int mt = blockIdx.x;
    if (mt * 64 >= ne) return;
    int row0  = g_off[e] + mt * 64;
    int valid = ne - mt * 64; if (valid > 64) valid = 64;
    int n0 = blockIdx.y * 64;

    __shared__ float As[16][64];
    __shared__ float Bs[16][64];

    int tid = threadIdx.x;
    int lm = tid >> 2, lk = (tid & 3) * 4;
    int bk = tid >> 4, bn = (tid & 15) * 4;
    int ty = (tid >> 4) * 4, tx = (tid & 15) * 4;

    const float* W2e = W2 + (size_t)e * NH * ND;
    const float* Arow = g_H + (size_t)(row0 + lm) * NH + lk;  // slack rows are valid memory

    float acc[4][4];
#pragma unroll
    for (int i = 0; i < 4; i++)
#pragma unroll
        for (int j = 0; j < 4; j++) acc[i][j] = 0.f;

    for (int k0 = 0; k0 < NH; k0 += 16) {
        float4 av = *(const float4*)(Arow + k0);
        As[lk + 0][lm] = av.x; As[lk + 1][lm] = av.y;
        As[lk + 2][lm] = av.z; As[lk + 3][lm] = av.w;
        *(float4*)&Bs[bk][bn] =
            *(const float4*)(W2e + (size_t)(k0 + bk) * ND + n0 + bn);
        __syncthreads();
#pragma unroll
        for (int k = 0; k < 16; k++) {
            float4 a = *(const float4*)&As[k][ty];
            float4 b = *(const float4*)&Bs[k][tx];
            float a4[4] = {a.x, a.y, a.z, a.w};
            float b4[4] = {b.x, b.y, b.z, b.w};
#pragma unroll
            for (int i = 0; i < 4; i++)
#pragma unroll
                for (int j = 0; j < 4; j++)
                    acc[i][j] = fmaf(a4[i], b4[j], acc[i][j]);
        }
        __syncthreads();
    }

#pragma unroll
    for (int i = 0; i < 4; i++) {
        if (ty + i < valid) {
            size_t row = (size_t)(row0 + ty + i);
#pragma unroll
            for (int j = 0; j < 4; j++) {
                int col = n0 + tx + j;
                g_Y[row * ND + col] = acc[i][j] + b2[e * ND + col];
            }
        }
    }
}

// ---------------- combine: out[t] = w0*Y[s0] + w1*Y[s1] ----------------------
__global__ __launch_bounds__(256) void k_combine(float* __restrict__ out) {
    int idx = blockIdx.x * 256 + threadIdx.x;    // NT*ND/4 threads
    int t = idx >> 8;            // ND/4 = 256 float4 per token
    int c = (idx & 255) << 2;
    float w0 = g_topw[t * 2 + 0], w1 = g_topw[t * 2 + 1];
    int   s0 = g_slot[t * 2 + 0], s1 = g_slot[t * 2 + 1];
    float4 y0 = *(const float4*)&g_Y[(size_t)s0 * ND + c];
    float4 y1 = *(const float4*)&g_Y[(size_t)s1 * ND + c];
    float4 o;
    o.x = w0 * y0.x + w1 * y1.x;
    o.y = w0 * y0.y + w1 * y1.y;
    o.z = w0 * y0.z + w1 * y1.z;
    o.w = w0 * y0.w + w1 * y1.w;
    *(float4*)&out[(size_t)t * ND + c] = o;
}

// ---------------- launch -----------------------------------------------------
extern "C" void kernel_launch(void* const* d_in, const int* in_sizes, int n_in,
                              void* d_out, int out_size) {
    const float* x  = (const float*)d_in[0];
    const float* Wg = (const float*)d_in[1];
    const float* W1 = (const float*)d_in[2];
    const float* b1 = (const float*)d_in[3];
    const float* W2 = (const float*)d_in[4];
    const float* b2 = (const float*)d_in[5];
    float* out = (float*)d_out;

    k_init<<<1, 32>>>();
    k_router<<<NT / 8, 256>>>(x, Wg);
    k_scan<<<1, 32>>>(out, out_size);
    k_fill<<<NT / 256, 256>>>();
    k_gemm1<<<dim3(NT / 64, NH / 64, NE), 256>>>(x, W1, b1);
    k_gemm2<<<dim3(NT / 64, ND / 64, NE), 256>>>(W2, b2);
    k_combine<<<NT * ND / 4 / 256, 256>>>(out);
}

// round 6
// speedup vs baseline: 1.6176x; 1.6176x over previous
#include <cuda_runtime.h>
#include <cuda_bf16.h>
#include <cstdint>
#include <math.h>

#define NE 8
#define NT 4096
#define ND 1024
#define NH 4096
#define SLOTP (2*NT+128)
#define BM 128
#define BN 64
#define BK 32
#define ROWW 20   // 32-bit words per smem row (16 data + 4 pad)

typedef __nv_bfloat16 bf16;

__device__ int   g_topi[NT*2];
__device__ float g_topw[NT*2];
__device__ int   g_cnt[NE];
__device__ float g_psum[NE];
__device__ int   g_off[NE+1];
__device__ int   g_cur[NE];
__device__ int   g_list[SLOTP];
__device__ int   g_slot[NT*2];
__device__ float g_H[(size_t)SLOTP*NH];
__device__ float g_Y[(size_t)SLOTP*ND];

#define MMA(d, a0, a1, a2, a3, b0, b1) asm volatile( \
    "mma.sync.aligned.m16n8k16.row.col.f32.bf16.bf16.f32 " \
    "{%0,%1,%2,%3}, {%4,%5,%6,%7}, {%8,%9}, {%0,%1,%2,%3};" \
    : "+f"((d)[0]),"+f"((d)[1]),"+f"((d)[2]),"+f"((d)[3]) \
    : "r"(a0),"r"(a1),"r"(a2),"r"(a3), "r"(b0),"r"(b1))

__device__ __forceinline__ uint32_t pack2(float x, float y) {
    return (uint32_t)__bfloat16_as_ushort(__float2bfloat16(x)) |
           ((uint32_t)__bfloat16_as_ushort(__float2bfloat16(y)) << 16);
}
__device__ __forceinline__ uint32_t pack2lo(float x, float y) {
    float xh = __bfloat162float(__float2bfloat16(x));
    float yh = __bfloat162float(__float2bfloat16(y));
    return pack2(x - xh, y - yh);
}

// ---------------- small kernels ----------------------------------------------
__global__ void k_init() {
    int i = threadIdx.x;
    if (i < NE) { g_cnt[i] = 0; g_psum[i] = 0.f; g_cur[i] = 0; }
}

__global__ __launch_bounds__(256) void k_router(const float* __restrict__ x,
                                                const float* __restrict__ Wg) {
    __shared__ float sW[NE * ND];
    int tid = threadIdx.x;
    for (int i = tid; i < NE * ND; i += 256) sW[i] = Wg[i];
    __syncthreads();
    int warp = tid >> 5, lane = tid & 31;
    int t = blockIdx.x * 8 + warp;
    float acc[NE];
#pragma unroll
    for (int e = 0; e < NE; e++) acc[e] = 0.f;
    const float* xr = x + (size_t)t * ND;
    for (int d = lane; d < ND; d += 32) {
        float xv = xr[d];
#pragma unroll
        for (int e = 0; e < NE; e++) acc[e] = fmaf(xv, sW[e * ND + d], acc[e]);
    }
#pragma unroll
    for (int e = 0; e < NE; e++)
#pragma unroll
        for (int o = 16; o; o >>= 1) acc[e] += __shfl_xor_sync(0xffffffffu, acc[e], o);
    if (lane == 0) {
        float mx = acc[0];
#pragma unroll
        for (int e = 1; e < NE; e++) mx = fmaxf(mx, acc[e]);
        float p[NE], Z = 0.f;
#pragma unroll
        for (int e = 0; e < NE; e++) { p[e] = expf(acc[e] - mx); Z += p[e]; }
        float inv = 1.f / Z;
#pragma unroll
        for (int e = 0; e < NE; e++) { p[e] *= inv; atomicAdd(&g_psum[e], p[e]); }
        int i0 = 0;
#pragma unroll
        for (int e = 1; e < NE; e++) if (p[e] > p[i0]) i0 = e;
        int i1 = (i0 == 0) ? 1 : 0;
#pragma unroll
        for (int e = 0; e < NE; e++) if (e != i0 && p[e] > p[i1]) i1 = e;
        float s = p[i0] + p[i1];
        g_topi[t*2] = i0; g_topi[t*2+1] = i1;
        g_topw[t*2] = p[i0] / s; g_topw[t*2+1] = p[i1] / s;
        atomicAdd(&g_cnt[i0], 1); atomicAdd(&g_cnt[i1], 1);
    }
}

__global__ void k_scan(float* __restrict__ out, int out_size) {
    if (threadIdx.x == 0) {
        int off = 0;
        for (int e = 0; e < NE; e++) { g_off[e] = off; off += g_cnt[e]; }
        g_off[NE] = off;
        float invT = 1.f / (float)NT, aux = 0.f;
        for (int e = 0; e < NE; e++) aux += ((float)g_cnt[e] * invT) * (g_psum[e] * invT);
        if (out_size > NT * ND) out[(size_t)NT * ND] = aux * (float)NE;
    }
}

__global__ void k_fill() {
    int t = blockIdx.x * blockDim.x + threadIdx.x;
    if (t >= NT) return;
#pragma unroll
    for (int k = 0; k < 2; k++) {
        int e = g_topi[t*2+k];
        int s = g_off[e] + atomicAdd(&g_cur[e], 1);
        g_list[s] = t;
        g_slot[t*2+k] = s;
    }
}

// ---------------- self-contained tensor-core grouped GEMM --------------------
// A: fp32, G1: x rows gathered via g_list; !G1: g_H rows direct.
// B: fp32 weights in native [k][n] layout (W1: [D][H], W2: [H][D]).
// In-kernel double-bf16 split; smem planes: A [m][k], B [n][k], 80B rows.
template<int KDIM, bool G1>
__global__ __launch_bounds__(256) void k_gemm(const float* __restrict__ x,
                                              const float* __restrict__ W,
                                              const float* __restrict__ bias) {
    int e = blockIdx.z;
    int ne = g_cnt[e];
    if ((int)blockIdx.x * BM >= ne) return;
    int row0 = g_off[e] + blockIdx.x * BM;
    int valid = min(BM, ne - (int)blockIdx.x * BM);
    int n0 = blockIdx.y * BN;

    __shared__ uint32_t sAh[BM*ROWW], sAl[BM*ROWW];
    __shared__ uint32_t sBh[BN*ROWW], sBl[BN*ROWW];

    int tid = threadIdx.x, wid = tid >> 5, lane = tid & 31;
    int wm = wid & 3, wn = wid >> 2;
    const int ldn = G1 ? NH : ND;

    // A loader geometry: one thread = one row-half (16 k values)
    int am = tid >> 1;
    int akh = (tid & 1) * 16;
    const float* arow;
    if (G1) arow = x + (size_t)g_list[row0 + am] * ND + akh;
    else    arow = g_H + (size_t)(row0 + am) * NH + akh;

    // B loader geometry: one thread = 2 k-rows x 4 n-values
    int bkp = tid >> 4;            // k-pair index 0..15
    int bnq = (tid & 15) * 4;      // n offset
    const float* brow = W + (size_t)e * ND * NH + (size_t)(2 * bkp) * ldn + n0 + bnq;

    float acc[2][4][4];
#pragma unroll
    for (int i = 0; i < 2; i++)
#pragma unroll
        for (int j = 0; j < 4; j++)
#pragma unroll
            for (int c = 0; c < 4; c++) acc[i][j][c] = 0.f;

    float ra[16];
    float4 rb0, rb1;

    auto ldA = [&](int kc) {
        const float4* p = (const float4*)(arow + kc * BK);
#pragma unroll
        for (int i = 0; i < 4; i++) *(float4*)&ra[i*4] = p[i];
    };
    auto ldB = [&](int kc) {
        const float* p = brow + (size_t)(kc * BK) * ldn;
        rb0 = *(const float4*)p;
        rb1 = *(const float4*)(p + ldn);
    };

    ldA(0); ldB(0);

    const int NK = KDIM / BK;
    for (int k = 0; k < NK; k++) {
        __syncthreads();
        // ---- STS: split + store ----
        {
            uint32_t h[8], l[8];
#pragma unroll
            for (int i = 0; i < 8; i++) {
                h[i] = pack2(ra[2*i], ra[2*i+1]);
                l[i] = pack2lo(ra[2*i], ra[2*i+1]);
            }
            uint32_t* dh = &sAh[am * ROWW + akh / 2];
            uint32_t* dl = &sAl[am * ROWW + akh / 2];
            *(uint4*)dh = make_uint4(h[0], h[1], h[2], h[3]);
            *(uint4*)(dh + 4) = make_uint4(h[4], h[5], h[6], h[7]);
            *(uint4*)dl = make_uint4(l[0], l[1], l[2], l[3]);
            *(uint4*)(dl + 4) = make_uint4(l[4], l[5], l[6], l[7]);

            const float* f0 = (const float*)&rb0;
            const float* f1 = (const float*)&rb1;
#pragma unroll
            for (int j = 0; j < 4; j++) {
                sBh[(bnq + j) * ROWW + bkp] = pack2(f0[j], f1[j]);
                sBl[(bnq + j) * ROWW + bkp] = pack2lo(f0[j], f1[j]);
            }
        }
        __syncthreads();
        if (k + 1 < NK) { ldA(k + 1); ldB(k + 1); }

        // ---- compute: 2 k16 steps ----
#pragma unroll
        for (int ks = 0; ks < 2; ks++) {
            int kb = ks * 8;
            uint32_t Ah[2][4], Al[2][4], Bh[4][2], Bl[4][2];
#pragma unroll
            for (int mt = 0; mt < 2; mt++) {
                int r = wm * 32 + mt * 16 + (lane >> 2);
                int w0 = r * ROWW + kb + (lane & 3);
                Ah[mt][0] = sAh[w0];            Ah[mt][1] = sAh[w0 + 8*ROWW];
                Ah[mt][2] = sAh[w0 + 4];        Ah[mt][3] = sAh[w0 + 8*ROWW + 4];
                Al[mt][0] = sAl[w0];            Al[mt][1] = sAl[w0 + 8*ROWW];
                Al[mt][2] = sAl[w0 + 4];        Al[mt][3] = sAl[w0 + 8*ROWW + 4];
            }
#pragma unroll
            for (int nb = 0; nb < 4; nb++) {
                int n = wn * 32 + nb * 8 + (lane >> 2);
                int w0 = n * ROWW + kb + (lane & 3);
                Bh[nb][0] = sBh[w0];  Bh[nb][1] = sBh[w0 + 4];
                Bl[nb][0] = sBl[w0];  Bl[nb][1] = sBl[w0 + 4];
            }
#pragma unroll
            for (int mt = 0; mt < 2; mt++)
#pragma unroll
                for (int nb = 0; nb < 4; nb++) {
                    MMA(acc[mt][nb], Ah[mt][0], Ah[mt][1], Ah[mt][2], Ah[mt][3],
                        Bh[nb][0], Bh[nb][1]);
                    MMA(acc[mt][nb], Ah[mt][0], Ah[mt][1], Ah[mt][2], Ah[mt][3],
                        Bl[nb][0], Bl[nb][1]);
                    MMA(acc[mt][nb], Al[mt][0], Al[mt][1], Al[mt][2], Al[mt][3],
                        Bh[nb][0], Bh[nb][1]);
                }
        }
    }

    // ---- epilogue ----
    int rb_ = lane >> 2;
    int cb = wn * 32 + (lane & 3) * 2;
#pragma unroll
    for (int mt = 0; mt < 2; mt++)
#pragma unroll
        for (int nb = 0; nb < 4; nb++) {
            int col = cb + nb * 8;
            float bv0 = bias[(size_t)e * ldn + n0 + col];
            float bv1 = bias[(size_t)e * ldn + n0 + col + 1];
#pragma unroll
            for (int h = 0; h < 2; h++) {
                int rloc = wm * 32 + mt * 16 + h * 8 + rb_;
                if (rloc < valid) {
                    float v0 = acc[mt][nb][h*2]   + bv0;
                    float v1 = acc[mt][nb][h*2+1] + bv1;
                    size_t go = (size_t)(row0 + rloc) * (size_t)ldn + n0 + col;
                    if (G1) {
                        v0 = v0 / (1.f + __expf(-v0));
                        v1 = v1 / (1.f + __expf(-v1));
                        *(float2*)&g_H[go] = make_float2(v0, v1);
                    } else {
                        *(float2*)&g_Y[go] = make_float2(v0, v1);
                    }
                }
            }
        }
}

// ---------------- combine ----------------------------------------------------
__global__ __launch_bounds__(256) void k_combine(float* __restrict__ out) {
    int idx = blockIdx.x * 256 + threadIdx.x;
    int t = idx >> 8;
    int c = (idx & 255) << 2;
    float w0 = g_topw[t*2], w1 = g_topw[t*2+1];
    int s0 = g_slot[t*2], s1 = g_slot[t*2+1];
    float4 y0 = *(const float4*)&g_Y[(size_t)s0 * ND + c];
    float4 y1 = *(const float4*)&g_Y[(size_t)s1 * ND + c];
    float4 o;
    o.x = w0*y0.x + w1*y1.x; o.y = w0*y0.y + w1*y1.y;
    o.z = w0*y0.z + w1*y1.z; o.w = w0*y0.w + w1*y1.w;
    *(float4*)&out[(size_t)t * ND + c] = o;
}

// ---------------- launch -----------------------------------------------------
extern "C" void kernel_launch(void* const* d_in, const int* in_sizes, int n_in,
                              void* d_out, int out_size) {
    const float* x  = (const float*)d_in[0];
    const float* Wg = (const float*)d_in[1];
    const float* W1 = (const float*)d_in[2];
    const float* b1 = (const float*)d_in[3];
    const float* W2 = (const float*)d_in[4];
    const float* b2 = (const float*)d_in[5];
    float* out = (float*)d_out;

    k_init<<<1, 32>>>();
    k_router<<<NT / 8, 256>>>(x, Wg);
    k_scan<<<1, 32>>>(out, out_size);
    k_fill<<<NT / 256, 256>>>();
    k_gemm<ND, true><<<dim3(64, NH / BN, NE), 256>>>(x, W1, b1);
    k_gemm<NH, false><<<dim3(64, ND / BN, NE), 256>>>(x, W2, b2);
    k_combine<<<NT * ND / 4 / 256, 256>>>(out);
}

// round 7
// speedup vs baseline: 1.8958x; 1.1720x over previous
#include <cuda_runtime.h>
#include <cuda_bf16.h>
#include <cstdint>
#include <math.h>

#define NE 8
#define NT 4096
#define ND 1024
#define NH 4096
#define SLOTP (2*NT+128)
#define BM 128
#define BN 128
#define BK 32
#define ROWW 20    // A smem: words per row (16 data + 4 pad)
#define BSTR 136   // B smem: words per kpair-row (128 data + 8 pad)

typedef __nv_bfloat16 bf16;

__device__ int   g_topi[NT*2];
__device__ float g_topw[NT*2];
__device__ int   g_cnt[NE];
__device__ float g_psum[NE];
__device__ int   g_off[NE+1];
__device__ int   g_cur[NE];
__device__ int   g_list[SLOTP];
__device__ int   g_slot[NT*2];
__device__ float g_H[(size_t)SLOTP*NH];
__device__ float g_Y[(size_t)SLOTP*ND];

#define MMA(d, a0, a1, a2, a3, b0, b1) asm volatile( \
    "mma.sync.aligned.m16n8k16.row.col.f32.bf16.bf16.f32 " \
    "{%0,%1,%2,%3}, {%4,%5,%6,%7}, {%8,%9}, {%0,%1,%2,%3};" \
    : "+f"((d)[0]),"+f"((d)[1]),"+f"((d)[2]),"+f"((d)[3]) \
    : "r"(a0),"r"(a1),"r"(a2),"r"(a3), "r"(b0),"r"(b1))

__device__ __forceinline__ uint32_t pack2(float x, float y) {
    return (uint32_t)__bfloat16_as_ushort(__float2bfloat16(x)) |
           ((uint32_t)__bfloat16_as_ushort(__float2bfloat16(y)) << 16);
}
__device__ __forceinline__ uint32_t pack2lo(float x, float y) {
    float xh = __bfloat162float(__float2bfloat16(x));
    float yh = __bfloat162float(__float2bfloat16(y));
    return pack2(x - xh, y - yh);
}

// ---------------- small kernels ----------------------------------------------
__global__ void k_init() {
    int i = threadIdx.x;
    if (i < NE) { g_cnt[i] = 0; g_psum[i] = 0.f; g_cur[i] = 0; }
}

__global__ __launch_bounds__(256) void k_router(const float* __restrict__ x,
                                                const float* __restrict__ Wg) {
    __shared__ float sW[NE * ND];
    int tid = threadIdx.x;
    for (int i = tid; i < NE * ND; i += 256) sW[i] = Wg[i];
    __syncthreads();
    int warp = tid >> 5, lane = tid & 31;
    int t = blockIdx.x * 8 + warp;
    float acc[NE];
#pragma unroll
    for (int e = 0; e < NE; e++) acc[e] = 0.f;
    const float* xr = x + (size_t)t * ND;
    for (int d = lane; d < ND; d += 32) {
        float xv = xr[d];
#pragma unroll
        for (int e = 0; e < NE; e++) acc[e] = fmaf(xv, sW[e * ND + d], acc[e]);
    }
#pragma unroll
    for (int e = 0; e < NE; e++)
#pragma unroll
        for (int o = 16; o; o >>= 1) acc[e] += __shfl_xor_sync(0xffffffffu, acc[e], o);
    if (lane == 0) {
        float mx = acc[0];
#pragma unroll
        for (int e = 1; e < NE; e++) mx = fmaxf(mx, acc[e]);
        float p[NE], Z = 0.f;
#pragma unroll
        for (int e = 0; e < NE; e++) { p[e] = expf(acc[e] - mx); Z += p[e]; }
        float inv = 1.f / Z;
#pragma unroll
        for (int e = 0; e < NE; e++) { p[e] *= inv; atomicAdd(&g_psum[e], p[e]); }
        int i0 = 0;
#pragma unroll
        for (int e = 1; e < NE; e++) if (p[e] > p[i0]) i0 = e;
        int i1 = (i0 == 0) ? 1 : 0;
#pragma unroll
        for (int e = 0; e < NE; e++) if (e != i0 && p[e] > p[i1]) i1 = e;
        float s = p[i0] + p[i1];
        g_topi[t*2] = i0; g_topi[t*2+1] = i1;
        g_topw[t*2] = p[i0] / s; g_topw[t*2+1] = p[i1] / s;
        atomicAdd(&g_cnt[i0], 1); atomicAdd(&g_cnt[i1], 1);
    }
}

__global__ void k_scan(float* __restrict__ out, int out_size) {
    if (threadIdx.x == 0) {
        int off = 0;
        for (int e = 0; e < NE; e++) { g_off[e] = off; off += g_cnt[e]; }
        g_off[NE] = off;
        float invT = 1.f / (float)NT, aux = 0.f;
        for (int e = 0; e < NE; e++) aux += ((float)g_cnt[e] * invT) * (g_psum[e] * invT);
        if (out_size > NT * ND) out[(size_t)NT * ND] = aux * (float)NE;
    }
}

__global__ void k_fill() {
    int t = blockIdx.x * blockDim.x + threadIdx.x;
    if (t >= NT) return;
#pragma unroll
    for (int k = 0; k < 2; k++) {
        int e = g_topi[t*2+k];
        int s = g_off[e] + atomicAdd(&g_cur[e], 1);
        g_list[s] = t;
        g_slot[t*2+k] = s;
    }
}

// ---------------- tensor-core grouped GEMM -----------------------------------
// A fp32 (G1: gathered x rows; else g_H). B fp32 native [k][n].
// In-register double-bf16 split. smem: A [m][kword] ROWW=20 pad;
// B [kpair][n] BSTR=136 pad (conflict-free STS + LDS).
template<int KDIM, bool G1>
__global__ __launch_bounds__(256) void k_gemm(const float* __restrict__ x,
                                              const float* __restrict__ W,
                                              const float* __restrict__ bias) {
    int e = blockIdx.z;
    int ne = g_cnt[e];
    if ((int)blockIdx.x * BM >= ne) return;
    int row0 = g_off[e] + blockIdx.x * BM;
    int valid = min(BM, ne - (int)blockIdx.x * BM);
    int n0 = blockIdx.y * BN;

    __shared__ __align__(16) uint32_t sAh[BM*ROWW], sAl[BM*ROWW];
    __shared__ __align__(16) uint32_t sBh[16*BSTR], sBl[16*BSTR];
    __shared__ float sbias[BN];

    int tid = threadIdx.x, wid = tid >> 5, lane = tid & 31;
    int wm = wid & 3, wn = wid >> 2;          // 4 x 2 warps, warp tile 32x64
    const int ldn = G1 ? NH : ND;

    if (tid < BN) sbias[tid] = bias[(size_t)e * ldn + n0 + tid];

    // A loader: thread = row-half (16 k values)
    int am = tid >> 1;
    int akh = (tid & 1) * 16;
    const float* arow;
    if (G1) arow = x + (size_t)g_list[row0 + am] * ND + akh;
    else    arow = g_H + (size_t)(row0 + am) * NH + akh;

    // B loader: thread = kpair (tid>>4) x 8 n-values ((tid&15)*8); coalesced 512B rows
    int bkp = tid >> 4;
    int bnq = (tid & 15) * 8;
    const float* brow = W + (size_t)e * ND * NH + (size_t)(2 * bkp) * ldn + n0 + bnq;

    float acc[2][8][4];
#pragma unroll
    for (int i = 0; i < 2; i++)
#pragma unroll
        for (int j = 0; j < 8; j++)
#pragma unroll
            for (int c = 0; c < 4; c++) acc[i][j][c] = 0.f;

    float ra[16];
    float rb0[8], rb1[8];

    auto ldA = [&](int kc) {
        const float4* p = (const float4*)(arow + kc * BK);
#pragma unroll
        for (int i = 0; i < 4; i++) *(float4*)&ra[i*4] = p[i];
    };
    auto ldB = [&](int kc) {
        const float* p = brow + (size_t)(kc * BK) * ldn;
        *(float4*)&rb0[0] = *(const float4*)p;
        *(float4*)&rb0[4] = *(const float4*)(p + 4);
        *(float4*)&rb1[0] = *(const float4*)(p + ldn);
        *(float4*)&rb1[4] = *(const float4*)(p + ldn + 4);
    };

    ldA(0); ldB(0);

    const int NK = KDIM / BK;
    for (int k = 0; k < NK; k++) {
        __syncthreads();
        // ---- STS: split + store (A: [m][kword]; B: [kpair][n]) ----
        {
            uint32_t h[8], l[8];
#pragma unroll
            for (int i = 0; i < 8; i++) {
                h[i] = pack2(ra[2*i], ra[2*i+1]);
                l[i] = pack2lo(ra[2*i], ra[2*i+1]);
            }
            uint32_t* dh = &sAh[am * ROWW + akh / 2];
            uint32_t* dl = &sAl[am * ROWW + akh / 2];
            *(uint4*)dh = make_uint4(h[0], h[1], h[2], h[3]);
            *(uint4*)(dh + 4) = make_uint4(h[4], h[5], h[6], h[7]);
            *(uint4*)dl = make_uint4(l[0], l[1], l[2], l[3]);
            *(uint4*)(dl + 4) = make_uint4(l[4], l[5], l[6], l[7]);

#pragma unroll
            for (int j = 0; j < 8; j++) {
                h[j] = pack2(rb0[j], rb1[j]);     // low = k, high = k+1
                l[j] = pack2lo(rb0[j], rb1[j]);
            }
            uint32_t* bh = &sBh[bkp * BSTR + bnq];
            uint32_t* bl = &sBl[bkp * BSTR + bnq];
            *(uint4*)bh = make_uint4(h[0], h[1], h[2], h[3]);
            *(uint4*)(bh + 4) = make_uint4(h[4], h[5], h[6], h[7]);
            *(uint4*)bl = make_uint4(l[0], l[1], l[2], l[3]);
            *(uint4*)(bl + 4) = make_uint4(l[4], l[5], l[6], l[7]);
        }
        __syncthreads();
        if (k + 1 < NK) { ldA(k + 1); ldB(k + 1); }

        // ---- compute: 2 k16 steps ----
#pragma unroll
        for (int ks = 0; ks < 2; ks++) {
            int kb = ks * 8;
            uint32_t Ah[2][4], Al[2][4], Bh[8][2], Bl[8][2];
#pragma unroll
            for (int mt = 0; mt < 2; mt++) {
                int r = wm * 32 + mt * 16 + (lane >> 2);
                int w0 = r * ROWW + kb + (lane & 3);
                Ah[mt][0] = sAh[w0];            Ah[mt][1] = sAh[w0 + 8*ROWW];
                Ah[mt][2] = sAh[w0 + 4];        Ah[mt][3] = sAh[w0 + 8*ROWW + 4];
                Al[mt][0] = sAl[w0];            Al[mt][1] = sAl[w0 + 8*ROWW];
                Al[mt][2] = sAl[w0 + 4];        Al[mt][3] = sAl[w0 + 8*ROWW + 4];
            }
            int kp0 = ks * 8 + (lane & 3);
#pragma unroll
            for (int nb = 0; nb < 8; nb++) {
                int n = wn * 64 + nb * 8 + (lane >> 2);
                Bh[nb][0] = sBh[kp0 * BSTR + n];
                Bh[nb][1] = sBh[(kp0 + 4) * BSTR + n];
                Bl[nb][0] = sBl[kp0 * BSTR + n];
                Bl[nb][1] = sBl[(kp0 + 4) * BSTR + n];
            }
#pragma unroll
            for (int mt = 0; mt < 2; mt++)
#pragma unroll
                for (int nb = 0; nb < 8; nb++) {
                    MMA(acc[mt][nb], Ah[mt][0], Ah[mt][1], Ah[mt][2], Ah[mt][3],
                        Bh[nb][0], Bh[nb][1]);
                    MMA(acc[mt][nb], Ah[mt][0], Ah[mt][1], Ah[mt][2], Ah[mt][3],
                        Bl[nb][0], Bl[nb][1]);
                    MMA(acc[mt][nb], Al[mt][0], Al[mt][1], Al[mt][2], Al[mt][3],
                        Bh[nb][0], Bh[nb][1]);
                }
        }
    }

    // ---- epilogue ----
    int rb_ = lane >> 2;
    int cb = wn * 64 + (lane & 3) * 2;
#pragma unroll
    for (int mt = 0; mt < 2; mt++)
#pragma unroll
        for (int nb = 0; nb < 8; nb++) {
            int col = cb + nb * 8;
            float bv0 = sbias[col], bv1 = sbias[col + 1];
#pragma unroll
            for (int h = 0; h < 2; h++) {
                int rloc = wm * 32 + mt * 16 + h * 8 + rb_;
                if (rloc < valid) {
                    float v0 = acc[mt][nb][h*2]   + bv0;
                    float v1 = acc[mt][nb][h*2+1] + bv1;
                    size_t go = (size_t)(row0 + rloc) * (size_t)ldn + n0 + col;
                    if (G1) {
                        v0 = v0 / (1.f + __expf(-v0));
                        v1 = v1 / (1.f + __expf(-v1));
                        *(float2*)&g_H[go] = make_float2(v0, v1);
                    } else {
                        *(float2*)&g_Y[go] = make_float2(v0, v1);
                    }
                }
            }
        }
}

// ---------------- combine ----------------------------------------------------
__global__ __launch_bounds__(256) void k_combine(float* __restrict__ out) {
    int idx = blockIdx.x * 256 + threadIdx.x;
    int t = idx >> 8;
    int c = (idx & 255) << 2;
    float w0 = g_topw[t*2], w1 = g_topw[t*2+1];
    int s0 = g_slot[t*2], s1 = g_slot[t*2+1];
    float4 y0 = *(const float4*)&g_Y[(size_t)s0 * ND + c];
    float4 y1 = *(const float4*)&g_Y[(size_t)s1 * ND + c];
    float4 o;
    o.x = w0*y0.x + w1*y1.x; o.y = w0*y0.y + w1*y1.y;
    o.z = w0*y0.z + w1*y1.z; o.w = w0*y0.w + w1*y1.w;
    *(float4*)&out[(size_t)t * ND + c] = o;
}

// ---------------- launch -----------------------------------------------------
extern "C" void kernel_launch(void* const* d_in, const int* in_sizes, int n_in,
                              void* d_out, int out_size) {
    const float* x  = (const float*)d_in[0];
    const float* Wg = (const float*)d_in[1];
    const float* W1 = (const float*)d_in[2];
    const float* b1 = (const float*)d_in[3];
    const float* W2 = (const float*)d_in[4];
    const float* b2 = (const float*)d_in[5];
    float* out = (float*)d_out;

    k_init<<<1, 32>>>();
    k_router<<<NT / 8, 256>>>(x, Wg);
    k_scan<<<1, 32>>>(out, out_size);
    k_fill<<<NT / 256, 256>>>();
    k_gemm<ND, true><<<dim3(64, NH / BN, NE), 256>>>(x, W1, b1);
    k_gemm<NH, false><<<dim3(64, ND / BN, NE), 256>>>(x, W2, b2);
    k_combine<<<NT * ND / 4 / 256, 256>>>(out);
}

// round 9
// speedup vs baseline: 2.4723x; 1.3041x over previous
#include <cuda_runtime.h>
#include <cuda_bf16.h>
#include <cstdint>
#include <math.h>

#define NE 8
#define NT 4096
#define ND 1024
#define NH 4096
#define SLOTP (2*NT+128)
#define BM 128
#define BN 256
#define BK 32
#define ROWW 20     // A smem words per row (16 data + 4 pad)
#define BSTR 264    // B smem words per kpair row (256 data + 8 pad)
#define SMEM_DYN 55296

typedef __nv_bfloat16 bf16;

__device__ int      g_topi[NT*2];
__device__ float    g_topw[NT*2];
__device__ int      g_cnt[NE];
__device__ float    g_psum[NE];
__device__ int      g_off[NE+1];
__device__ int      g_cur[NE];
__device__ int      g_list[SLOTP];
__device__ int      g_slot[NT*2];
__device__ uint32_t g_AhW[(size_t)SLOTP*(ND/2)],  g_AlW[(size_t)SLOTP*(ND/2)];
__device__ uint32_t g_W1h[(size_t)NE*(ND/2)*NH], g_W1l[(size_t)NE*(ND/2)*NH];
__device__ uint32_t g_W2h[(size_t)NE*(NH/2)*ND], g_W2l[(size_t)NE*(NH/2)*ND];
__device__ uint32_t g_HhW[(size_t)SLOTP*(NH/2)], g_HlW[(size_t)SLOTP*(NH/2)];
__device__ float    g_Y[(size_t)SLOTP*ND];

#define MMA(d, a0, a1, a2, a3, b0, b1) asm volatile( \
    "mma.sync.aligned.m16n8k16.row.col.f32.bf16.bf16.f32 " \
    "{%0,%1,%2,%3}, {%4,%5,%6,%7}, {%8,%9}, {%0,%1,%2,%3};" \
    : "+f"((d)[0]),"+f"((d)[1]),"+f"((d)[2]),"+f"((d)[3]) \
    : "r"(a0),"r"(a1),"r"(a2),"r"(a3), "r"(b0),"r"(b1))

__device__ __forceinline__ uint32_t pack2(float x, float y) {
    return (uint32_t)__bfloat16_as_ushort(__float2bfloat16(x)) |
           ((uint32_t)__bfloat16_as_ushort(__float2bfloat16(y)) << 16);
}
__device__ __forceinline__ uint32_t pack2lo(float x, float y) {
    float xh = __bfloat162float(__float2bfloat16(x));
    float yh = __bfloat162float(__float2bfloat16(y));
    return pack2(x - xh, y - yh);
}

// ---------------- small kernels ----------------------------------------------
__global__ void k_init() {
    int i = threadIdx.x;
    if (i < NE) { g_cnt[i] = 0; g_psum[i] = 0.f; g_cur[i] = 0; }
}

__global__ __launch_bounds__(256) void k_router(const float* __restrict__ x,
                                                const float* __restrict__ Wg) {
    __shared__ float sW[NE * ND];
    int tid = threadIdx.x;
    for (int i = tid; i < NE * ND; i += 256) sW[i] = Wg[i];
    __syncthreads();
    int warp = tid >> 5, lane = tid & 31;
    int t = blockIdx.x * 8 + warp;
    float acc[NE];
#pragma unroll
    for (int e = 0; e < NE; e++) acc[e] = 0.f;
    const float* xr = x + (size_t)t * ND;
    for (int d = lane; d < ND; d += 32) {
        float xv = xr[d];
#pragma unroll
        for (int e = 0; e < NE; e++) acc[e] = fmaf(xv, sW[e * ND + d], acc[e]);
    }
#pragma unroll
    for (int e = 0; e < NE; e++)
#pragma unroll
        for (int o = 16; o; o >>= 1) acc[e] += __shfl_xor_sync(0xffffffffu, acc[e], o);
    if (lane == 0) {
        float mx = acc[0];
#pragma unroll
        for (int e = 1; e < NE; e++) mx = fmaxf(mx, acc[e]);
        float p[NE], Z = 0.f;
#pragma unroll
        for (int e = 0; e < NE; e++) { p[e] = expf(acc[e] - mx); Z += p[e]; }
        float inv = 1.f / Z;
#pragma unroll
        for (int e = 0; e < NE; e++) { p[e] *= inv; atomicAdd(&g_psum[e], p[e]); }
        int i0 = 0;
#pragma unroll
        for (int e = 1; e < NE; e++) if (p[e] > p[i0]) i0 = e;
        int i1 = (i0 == 0) ? 1 : 0;
#pragma unroll
        for (int e = 0; e < NE; e++) if (e != i0 && p[e] > p[i1]) i1 = e;
        float s = p[i0] + p[i1];
        g_topi[t*2] = i0; g_topi[t*2+1] = i1;
        g_topw[t*2] = p[i0] / s; g_topw[t*2+1] = p[i1] / s;
        atomicAdd(&g_cnt[i0], 1); atomicAdd(&g_cnt[i1], 1);
    }
}

__global__ void k_scan(float* __restrict__ out, int out_size) {
    if (threadIdx.x == 0) {
        int off = 0;
        for (int e = 0; e < NE; e++) { g_off[e] = off; off += g_cnt[e]; }
        g_off[NE] = off;
        float invT = 1.f / (float)NT, aux = 0.f;
        for (int e = 0; e < NE; e++) aux += ((float)g_cnt[e] * invT) * (g_psum[e] * invT);
        if (out_size > NT * ND) out[(size_t)NT * ND] = aux * (float)NE;
    }
}

__global__ void k_fill() {
    int t = blockIdx.x * blockDim.x + threadIdx.x;
    if (t >= NT) return;
#pragma unroll
    for (int k = 0; k < 2; k++) {
        int e = g_topi[t*2+k];
        int s = g_off[e] + atomicAdd(&g_cur[e], 1);
        g_list[s] = t;
        g_slot[t*2+k] = s;
    }
}

// gather + split + pair-pack x
__global__ __launch_bounds__(256) void k_gather(const float* __restrict__ x) {
    int idx = blockIdx.x * 256 + threadIdx.x;
    int slot = idx >> 7;
    int q = (idx & 127) * 8;
    int t = g_list[slot];
    const float* p = x + (size_t)t * ND + q;
    float4 v0 = *(const float4*)p;
    float4 v1 = *(const float4*)(p + 4);
    uint4 h = make_uint4(pack2(v0.x, v0.y), pack2(v0.z, v0.w),
                         pack2(v1.x, v1.y), pack2(v1.z, v1.w));
    uint4 l = make_uint4(pack2lo(v0.x, v0.y), pack2lo(v0.z, v0.w),
                         pack2lo(v1.x, v1.y), pack2lo(v1.z, v1.w));
    size_t o = (size_t)slot * (ND/2) + q/2;
    *(uint4*)&g_AhW[o] = h;
    *(uint4*)&g_AlW[o] = l;
}

// split + pair-pack W (device-side global selection — NOT host-passed symbols)
template<int K, int N, bool FIRST>
__global__ __launch_bounds__(256) void k_split(const float* __restrict__ W) {
    uint32_t* __restrict__ Wh = FIRST ? g_W1h : g_W2h;
    uint32_t* __restrict__ Wl = FIRST ? g_W1l : g_W2l;
    int e = blockIdx.y;
    int idx = blockIdx.x * 256 + threadIdx.x;
    int kp = idx / (N/4);
    int nq = (idx % (N/4)) * 4;
    const float* p = W + ((size_t)e * K + 2*kp) * N + nq;
    float4 r0 = *(const float4*)p;
    float4 r1 = *(const float4*)(p + N);
    uint4 h = make_uint4(pack2(r0.x, r1.x), pack2(r0.y, r1.y),
                         pack2(r0.z, r1.z), pack2(r0.w, r1.w));
    uint4 l = make_uint4(pack2lo(r0.x, r1.x), pack2lo(r0.y, r1.y),
                         pack2lo(r0.z, r1.z), pack2lo(r0.w, r1.w));
    size_t o = ((size_t)e * (K/2) + kp) * N + nq;
    *(uint4*)&Wh[o] = h;
    *(uint4*)&Wl[o] = l;
}

// ---------------- tensor-core grouped GEMM (pre-split bf16 inputs) -----------
template<int KDIM, bool G1>
__global__ __launch_bounds__(256) void k_gemm(const float* __restrict__ bias) {
    const int KW = KDIM / 2;
    int e = blockIdx.z;
    int ne = g_cnt[e];
    if ((int)blockIdx.x * BM >= ne) return;
    int row0 = g_off[e] + blockIdx.x * BM;
    int valid = min(BM, ne - (int)blockIdx.x * BM);
    int n0 = blockIdx.y * BN;

    extern __shared__ uint32_t sm[];
    uint32_t* sAh = sm;
    uint32_t* sAl = sm + 2560;
    uint32_t* sBh = sm + 5120;
    uint32_t* sBl = sm + 9344;
    float* sbias  = (float*)(sm + 13568);

    int tid = threadIdx.x, wid = tid >> 5, lane = tid & 31;
    int wm2 = wid & 1, wn = wid >> 1;
    const int ldn = G1 ? NH : ND;

    sbias[tid] = bias[(size_t)e * ldn + n0 + tid];

    const uint32_t* aH = (G1 ? g_AhW : g_HhW);
    const uint32_t* aL = (G1 ? g_AlW : g_HlW);
    const uint32_t* bH = (G1 ? g_W1h : g_W2h);
    const uint32_t* bL = (G1 ? g_W1l : g_W2l);

    int am = tid >> 1, half = tid & 1;
    const uint32_t* arH = aH + (size_t)(row0 + am) * KW + half * 8;
    const uint32_t* arL = aL + (size_t)(row0 + am) * KW + half * 8;
    int bkp = tid >> 4, bt = tid & 15;
    const uint32_t* brH = bH + ((size_t)e * KW + bkp) * ldn + n0 + bt * 8;
    const uint32_t* brL = bL + ((size_t)e * KW + bkp) * ldn + n0 + bt * 8;

    float acc[4][8][4];
#pragma unroll
    for (int i = 0; i < 4; i++)
#pragma unroll
        for (int j = 0; j < 8; j++)
#pragma unroll
            for (int c = 0; c < 4; c++) acc[i][j][c] = 0.f;

    uint4 sa[4], sb[8];
    auto ldA = [&](int kc) {
        const uint32_t* p = arH + kc * 16;
        sa[0] = *(const uint4*)p;       sa[1] = *(const uint4*)(p + 4);
        p = arL + kc * 16;
        sa[2] = *(const uint4*)p;       sa[3] = *(const uint4*)(p + 4);
    };
    auto ldB = [&](int kc) {
        const uint32_t* p = brH + (size_t)(kc * 16) * ldn;
        sb[0] = *(const uint4*)p;         sb[1] = *(const uint4*)(p + 4);
        sb[2] = *(const uint4*)(p + 128); sb[3] = *(const uint4*)(p + 132);
        p = brL + (size_t)(kc * 16) * ldn;
        sb[4] = *(const uint4*)p;         sb[5] = *(const uint4*)(p + 4);
        sb[6] = *(const uint4*)(p + 128); sb[7] = *(const uint4*)(p + 132);
    };

    ldA(0); ldB(0);

    const int NK = KDIM / BK;
    for (int k = 0; k < NK; k++) {
        __syncthreads();
        {   // STS (pure copies)
            uint32_t* d = &sAh[am * ROWW + half * 8];
            *(uint4*)d = sa[0]; *(uint4*)(d + 4) = sa[1];
            d = &sAl[am * ROWW + half * 8];
            *(uint4*)d = sa[2]; *(uint4*)(d + 4) = sa[3];
            d = &sBh[bkp * BSTR + bt * 8];
            *(uint4*)d = sb[0]; *(uint4*)(d + 4) = sb[1];
            *(uint4*)(d + 128) = sb[2]; *(uint4*)(d + 132) = sb[3];
            d = &sBl[bkp * BSTR + bt * 8];
            *(uint4*)d = sb[4]; *(uint4*)(d + 4) = sb[5];
            *(uint4*)(d + 128) = sb[6]; *(uint4*)(d + 132) = sb[7];
        }
        __syncthreads();
        if (k + 1 < NK) { ldA(k + 1); ldB(k + 1); }

#pragma unroll
        for (int ks = 0; ks < 2; ks++) {
            int kb = ks * 8;
            uint32_t Ah[4][4], Al[4][4];
#pragma unroll
            for (int mt = 0; mt < 4; mt++) {
                int r = wm2 * 64 + mt * 16 + (lane >> 2);
                int w0 = r * ROWW + kb + (lane & 3);
                Ah[mt][0] = sAh[w0];      Ah[mt][1] = sAh[w0 + 8*ROWW];
                Ah[mt][2] = sAh[w0 + 4];  Ah[mt][3] = sAh[w0 + 8*ROWW + 4];
                Al[mt][0] = sAl[w0];      Al[mt][1] = sAl[w0 + 8*ROWW];
                Al[mt][2] = sAl[w0 + 4];  Al[mt][3] = sAl[w0 + 8*ROWW + 4];
            }
            int kp0 = kb + (lane & 3);
#pragma unroll
            for (int nb = 0; nb < 8; nb++) {
                int n = wn * 64 + nb * 8 + (lane >> 2);
                uint32_t b0h = sBh[kp0 * BSTR + n];
                uint32_t b1h = sBh[(kp0 + 4) * BSTR + n];
                uint32_t b0l = sBl[kp0 * BSTR + n];
                uint32_t b1l = sBl[(kp0 + 4) * BSTR + n];
#pragma unroll
                for (int mt = 0; mt < 4; mt++) {
                    MMA(acc[mt][nb], Ah[mt][0], Ah[mt][1], Ah[mt][2], Ah[mt][3], b0h, b1h);
                    MMA(acc[mt][nb], Ah[mt][0], Ah[mt][1], Ah[mt][2], Ah[mt][3], b0l, b1l);
                    MMA(acc[mt][nb], Al[mt][0], Al[mt][1], Al[mt][2], Al[mt][3], b0h, b1h);
                }
            }
        }
    }

    // ---- epilogue ----
    int rb_ = lane >> 2;
    int cb = wn * 64 + (lane & 3) * 2;
#pragma unroll
    for (int mt = 0; mt < 4; mt++)
#pragma unroll
        for (int nb = 0; nb < 8; nb++) {
            int col = cb + nb * 8;
            float bv0 = sbias[col], bv1 = sbias[col + 1];
#pragma unroll
            for (int h = 0; h < 2; h++) {
                int rloc = wm2 * 64 + mt * 16 + h * 8 + rb_;
                if (rloc < valid) {
                    float v0 = acc[mt][nb][h*2]   + bv0;
                    float v1 = acc[mt][nb][h*2+1] + bv1;
                    if (G1) {
                        v0 = v0 / (1.f + __expf(-v0));
                        v1 = v1 / (1.f + __expf(-v1));
                        size_t go = (size_t)(row0 + rloc) * (NH/2) + (n0 + col)/2;
                        g_HhW[go] = pack2(v0, v1);
                        g_HlW[go] = pack2lo(v0, v1);
                    } else {
                        size_t go = (size_t)(row0 + rloc) * ND + n0 + col;
                        *(float2*)&g_Y[go] = make_float2(v0, v1);
                    }
                }
            }
        }
}

// ---------------- combine ----------------------------------------------------
__global__ __launch_bounds__(256) void k_combine(float* __restrict__ out) {
    int idx = blockIdx.x * 256 + threadIdx.x;
    int t = idx >> 8;
    int c = (idx & 255) << 2;
    float w0 = g_topw[t*2], w1 = g_topw[t*2+1];
    int s0 = g_slot[t*2], s1 = g_slot[t*2+1];
    float4 y0 = *(const float4*)&g_Y[(size_t)s0 * ND + c];
    float4 y1 = *(const float4*)&g_Y[(size_t)s1 * ND + c];
    float4 o;
    o.x = w0*y0.x + w1*y1.x; o.y = w0*y0.y + w1*y1.y;
    o.z = w0*y0.z + w1*y1.z; o.w = w0*y0.w + w1*y1.w;
    *(float4*)&out[(size_t)t * ND + c] = o;
}

// ---------------- launch -----------------------------------------------------
extern "C" void kernel_launch(void* const* d_in, const int* in_sizes, int n_in,
                              void* d_out, int out_size) {
    const float* x  = (const float*)d_in[0];
    const float* Wg = (const float*)d_in[1];
    const float* W1 = (const float*)d_in[2];
    const float* b1 = (const float*)d_in[3];
    const float* W2 = (const float*)d_in[4];
    const float* b2 = (const float*)d_in[5];
    float* out = (float*)d_out;

    cudaFuncSetAttribute(k_gemm<ND, true>,  cudaFuncAttributeMaxDynamicSharedMemorySize, SMEM_DYN);
    cudaFuncSetAttribute(k_gemm<NH, false>, cudaFuncAttributeMaxDynamicSharedMemorySize, SMEM_DYN);

    k_init<<<1, 32>>>();
    k_router<<<NT / 8, 256>>>(x, Wg);
    k_scan<<<1, 32>>>(out, out_size);
    k_fill<<<NT / 256, 256>>>();
    k_gather<<<2 * NT * 128 / 256, 256>>>(x);
    k_split<ND, NH, true ><<<dim3((ND/2)*(NH/4)/256, NE), 256>>>(W1);
    k_split<NH, ND, false><<<dim3((NH/2)*(ND/4)/256, NE), 256>>>(W2);
    k_gemm<ND, true><<<dim3(64, NH / BN, NE), 256, SMEM_DYN>>>(b1);
    k_gemm<NH, false><<<dim3(64, ND / BN, NE), 256, SMEM_DYN>>>(b2);
    k_combine<<<NT * ND / 4 / 256, 256>>>(out);
}

// round 10
// speedup vs baseline: 2.4917x; 1.0078x over previous
#include <cuda_runtime.h>
#include <cuda_bf16.h>
#include <cstdint>
#include <math.h>

#define NE 8
#define NT 4096
#define ND 1024
#define NH 4096
#define SLOTP (2*NT+128)
#define BM 128
#define BN 256
#define BK 32
#define ROWW 20     // A smem words per row (16 data + 4 pad)
#define BSTR 264    // B smem words per kpair row (256 data + 8 pad)
#define STGW 13568  // words per stage (2*2560 + 2*4224)
#define SMEM_DYN (3*STGW*4)

typedef __nv_bfloat16 bf16;

__device__ int      g_topi[NT*2];
__device__ float    g_topw[NT*2];
__device__ int      g_cnt[NE];
__device__ float    g_psum[NE];
__device__ int      g_off[NE+1];
__device__ int      g_cur[NE];
__device__ int      g_list[SLOTP];
__device__ int      g_slot[NT*2];
__device__ uint32_t g_AhW[(size_t)SLOTP*(ND/2)],  g_AlW[(size_t)SLOTP*(ND/2)];
__device__ uint32_t g_W1h[(size_t)NE*(ND/2)*NH], g_W1l[(size_t)NE*(ND/2)*NH];
__device__ uint32_t g_W2h[(size_t)NE*(NH/2)*ND], g_W2l[(size_t)NE*(NH/2)*ND];
__device__ uint32_t g_HhW[(size_t)SLOTP*(NH/2)], g_HlW[(size_t)SLOTP*(NH/2)];
__device__ float    g_Y[(size_t)SLOTP*ND];

__device__ __forceinline__ uint32_t smem_u32(const void* p) {
    uint32_t a;
    asm("{ .reg .u64 t; cvta.to.shared.u64 t, %1; cvt.u32.u64 %0, t; }" : "=r"(a) : "l"(p));
    return a;
}
#define CP16(d, s) asm volatile("cp.async.cg.shared.global [%0], [%1], 16;" :: "r"(d), "l"(s))
#define CPCOMMIT() asm volatile("cp.async.commit_group;" ::: "memory")
#define CPWAIT1()  asm volatile("cp.async.wait_group 1;" ::: "memory")

#define MMA(d, a0, a1, a2, a3, b0, b1) asm volatile( \
    "mma.sync.aligned.m16n8k16.row.col.f32.bf16.bf16.f32 " \
    "{%0,%1,%2,%3}, {%4,%5,%6,%7}, {%8,%9}, {%0,%1,%2,%3};" \
    : "+f"((d)[0]),"+f"((d)[1]),"+f"((d)[2]),"+f"((d)[3]) \
    : "r"(a0),"r"(a1),"r"(a2),"r"(a3), "r"(b0),"r"(b1))

__device__ __forceinline__ uint32_t pack2(float x, float y) {
    return (uint32_t)__bfloat16_as_ushort(__float2bfloat16(x)) |
           ((uint32_t)__bfloat16_as_ushort(__float2bfloat16(y)) << 16);
}
__device__ __forceinline__ uint32_t pack2lo(float x, float y) {
    float xh = __bfloat162float(__float2bfloat16(x));
    float yh = __bfloat162float(__float2bfloat16(y));
    return pack2(x - xh, y - yh);
}

// ---------------- small kernels ----------------------------------------------
__global__ void k_init() {
    int i = threadIdx.x;
    if (i < NE) { g_cnt[i] = 0; g_psum[i] = 0.f; g_cur[i] = 0; }
}

__global__ __launch_bounds__(256) void k_router(const float* __restrict__ x,
                                                const float* __restrict__ Wg) {
    __shared__ float sW[NE * ND];
    int tid = threadIdx.x;
    for (int i = tid; i < NE * ND; i += 256) sW[i] = Wg[i];
    __syncthreads();
    int warp = tid >> 5, lane = tid & 31;
    int t = blockIdx.x * 8 + warp;
    float acc[NE];
#pragma unroll
    for (int e = 0; e < NE; e++) acc[e] = 0.f;
    const float* xr = x + (size_t)t * ND;
    for (int d = lane; d < ND; d += 32) {
        float xv = xr[d];
#pragma unroll
        for (int e = 0; e < NE; e++) acc[e] = fmaf(xv, sW[e * ND + d], acc[e]);
    }
#pragma unroll
    for (int e = 0; e < NE; e++)
#pragma unroll
        for (int o = 16; o; o >>= 1) acc[e] += __shfl_xor_sync(0xffffffffu, acc[e], o);
    if (lane == 0) {
        float mx = acc[0];
#pragma unroll
        for (int e = 1; e < NE; e++) mx = fmaxf(mx, acc[e]);
        float p[NE], Z = 0.f;
#pragma unroll
        for (int e = 0; e < NE; e++) { p[e] = expf(acc[e] - mx); Z += p[e]; }
        float inv = 1.f / Z;
#pragma unroll
        for (int e = 0; e < NE; e++) { p[e] *= inv; atomicAdd(&g_psum[e], p[e]); }
        int i0 = 0;
#pragma unroll
        for (int e = 1; e < NE; e++) if (p[e] > p[i0]) i0 = e;
        int i1 = (i0 == 0) ? 1 : 0;
#pragma unroll
        for (int e = 0; e < NE; e++) if (e != i0 && p[e] > p[i1]) i1 = e;
        float s = p[i0] + p[i1];
        g_topi[t*2] = i0; g_topi[t*2+1] = i1;
        g_topw[t*2] = p[i0] / s; g_topw[t*2+1] = p[i1] / s;
        atomicAdd(&g_cnt[i0], 1); atomicAdd(&g_cnt[i1], 1);
    }
}

__global__ void k_scan(float* __restrict__ out, int out_size) {
    if (threadIdx.x == 0) {
        int off = 0;
        for (int e = 0; e < NE; e++) { g_off[e] = off; off += g_cnt[e]; }
        g_off[NE] = off;
        float invT = 1.f / (float)NT, aux = 0.f;
        for (int e = 0; e < NE; e++) aux += ((float)g_cnt[e] * invT) * (g_psum[e] * invT);
        if (out_size > NT * ND) out[(size_t)NT * ND] = aux * (float)NE;
    }
}

__global__ void k_fill() {
    int t = blockIdx.x * blockDim.x + threadIdx.x;
    if (t >= NT) return;
#pragma unroll
    for (int k = 0; k < 2; k++) {
        int e = g_topi[t*2+k];
        int s = g_off[e] + atomicAdd(&g_cur[e], 1);
        g_list[s] = t;
        g_slot[t*2+k] = s;
    }
}

// gather + split + pair-pack x
__global__ __launch_bounds__(256) void k_gather(const float* __restrict__ x) {
    int idx = blockIdx.x * 256 + threadIdx.x;
    int slot = idx >> 7;
    int q = (idx & 127) * 8;
    int t = g_list[slot];
    const float* p = x + (size_t)t * ND + q;
    float4 v0 = *(const float4*)p;
    float4 v1 = *(const float4*)(p + 4);
    uint4 h = make_uint4(pack2(v0.x, v0.y), pack2(v0.z, v0.w),
                         pack2(v1.x, v1.y), pack2(v1.z, v1.w));
    uint4 l = make_uint4(pack2lo(v0.x, v0.y), pack2lo(v0.z, v0.w),
                         pack2lo(v1.x, v1.y), pack2lo(v1.z, v1.w));
    size_t o = (size_t)slot * (ND/2) + q/2;
    *(uint4*)&g_AhW[o] = h;
    *(uint4*)&g_AlW[o] = l;
}

// split + pair-pack W (device-side global selection — NOT host-passed symbols)
template<int K, int N, bool FIRST>
__global__ __launch_bounds__(256) void k_split(const float* __restrict__ W) {
    uint32_t* __restrict__ Wh = FIRST ? g_W1h : g_W2h;
    uint32_t* __restrict__ Wl = FIRST ? g_W1l : g_W2l;
    int e = blockIdx.y;
    int idx = blockIdx.x * 256 + threadIdx.x;
    int kp = idx / (N/4);
    int nq = (idx % (N/4)) * 4;
    const float* p = W + ((size_t)e * K + 2*kp) * N + nq;
    float4 r0 = *(const float4*)p;
    float4 r1 = *(const float4*)(p + N);
    uint4 h = make_uint4(pack2(r0.x, r1.x), pack2(r0.y, r1.y),
                         pack2(r0.z, r1.z), pack2(r0.w, r1.w));
    uint4 l = make_uint4(pack2lo(r0.x, r1.x), pack2lo(r0.y, r1.y),
                         pack2lo(r0.z, r1.z), pack2lo(r0.w, r1.w));
    size_t o = ((size_t)e * (K/2) + kp) * N + nq;
    *(uint4*)&Wh[o] = h;
    *(uint4*)&Wl[o] = l;
}

// ---------------- tensor-core grouped GEMM (cp.async 3-stage) ----------------
template<int KDIM, bool G1>
__global__ __launch_bounds__(256) void k_gemm(const float* __restrict__ bias) {
    const int KW = KDIM / 2;
    int e = blockIdx.z;
    int ne = g_cnt[e];
    if ((int)blockIdx.x * BM >= ne) return;
    int row0 = g_off[e] + blockIdx.x * BM;
    int valid = min(BM, ne - (int)blockIdx.x * BM);
    int n0 = blockIdx.y * BN;

    extern __shared__ uint32_t sm[];
    __shared__ float sbias[BN];
    uint32_t sbase = smem_u32(sm);

    int tid = threadIdx.x, wid = tid >> 5, lane = tid & 31;
    int wm2 = wid & 1, wn = wid >> 1;
    const int ldn = G1 ? NH : ND;

    sbias[tid] = bias[(size_t)e * ldn + n0 + tid];

    const uint32_t* aH = (G1 ? g_AhW : g_HhW);
    const uint32_t* aL = (G1 ? g_AlW : g_HlW);
    const uint32_t* bH = (G1 ? g_W1h : g_W2h);
    const uint32_t* bL = (G1 ? g_W1l : g_W2l);

    int am = tid >> 1, half = tid & 1;
    const uint32_t* arH = aH + (size_t)(row0 + am) * KW + half * 8;
    const uint32_t* arL = aL + (size_t)(row0 + am) * KW + half * 8;
    int bkp = tid >> 4, bt = tid & 15;
    const uint32_t* brH = bH + ((size_t)e * KW + bkp) * ldn + n0 + bt * 8;
    const uint32_t* brL = bL + ((size_t)e * KW + bkp) * ldn + n0 + bt * 8;

    uint32_t aoff = (uint32_t)(am * ROWW + half * 8) * 4u;
    uint32_t boff = (uint32_t)(bkp * BSTR + bt * 8) * 4u;

    auto load_stage = [&](int s, int kc) {
        uint32_t st = sbase + (uint32_t)s * (STGW * 4u);
        const uint32_t* pa = arH + (size_t)kc * 16;
        CP16(st + aoff, pa);          CP16(st + aoff + 16, pa + 4);
        pa = arL + (size_t)kc * 16;
        CP16(st + 10240 + aoff, pa);  CP16(st + 10240 + aoff + 16, pa + 4);
        const uint32_t* pb = brH + (size_t)(kc * 16) * ldn;
        uint32_t db = st + 20480 + boff;
        CP16(db, pb);        CP16(db + 16, pb + 4);
        CP16(db + 512, pb + 128); CP16(db + 528, pb + 132);
        pb = brL + (size_t)(kc * 16) * ldn;
        db += 16896;
        CP16(db, pb);        CP16(db + 16, pb + 4);
        CP16(db + 512, pb + 128); CP16(db + 528, pb + 132);
    };

    float acc[4][8][4];
#pragma unroll
    for (int i = 0; i < 4; i++)
#pragma unroll
        for (int j = 0; j < 8; j++)
#pragma unroll
            for (int c = 0; c < 4; c++) acc[i][j][c] = 0.f;

    load_stage(0, 0); CPCOMMIT();
    load_stage(1, 1); CPCOMMIT();

    const int NK = KDIM / BK;
    int ks3 = 0;
    for (int k = 0; k < NK; k++) {
        CPWAIT1();
        __syncthreads();
        if (k + 2 < NK) load_stage((ks3 + 2) % 3, k + 2);
        CPCOMMIT();

        uint32_t* stg = sm + ks3 * STGW;
        uint32_t* sAh = stg;
        uint32_t* sAl = stg + 2560;
        uint32_t* sBh = stg + 5120;
        uint32_t* sBl = stg + 9344;

#pragma unroll
        for (int ks = 0; ks < 2; ks++) {
            int kb = ks * 8;
            uint32_t Ah[4][4], Al[4][4];
#pragma unroll
            for (int mt = 0; mt < 4; mt++) {
                int r = wm2 * 64 + mt * 16 + (lane >> 2);
                int w0 = r * ROWW + kb + (lane & 3);
                Ah[mt][0] = sAh[w0];      Ah[mt][1] = sAh[w0 + 8*ROWW];
                Ah[mt][2] = sAh[w0 + 4];  Ah[mt][3] = sAh[w0 + 8*ROWW + 4];
                Al[mt][0] = sAl[w0];      Al[mt][1] = sAl[w0 + 8*ROWW];
                Al[mt][2] = sAl[w0 + 4];  Al[mt][3] = sAl[w0 + 8*ROWW + 4];
            }
            int kp0 = kb + (lane & 3);
#pragma unroll
            for (int nb = 0; nb < 8; nb++) {
                int n = wn * 64 + nb * 8 + (lane >> 2);
                uint32_t b0h = sBh[kp0 * BSTR + n];
                uint32_t b1h = sBh[(kp0 + 4) * BSTR + n];
                uint32_t b0l = sBl[kp0 * BSTR + n];
                uint32_t b1l = sBl[(kp0 + 4) * BSTR + n];
#pragma unroll
                for (int mt = 0; mt < 4; mt++) {
                    MMA(acc[mt][nb], Ah[mt][0], Ah[mt][1], Ah[mt][2], Ah[mt][3], b0h, b1h);
                    MMA(acc[mt][nb], Ah[mt][0], Ah[mt][1], Ah[mt][2], Ah[mt][3], b0l, b1l);
                    MMA(acc[mt][nb], Al[mt][0], Al[mt][1], Al[mt][2], Al[mt][3], b0h, b1h);
                }
            }
        }
        ks3 = (ks3 + 1) % 3;
    }

    // ---- epilogue ----
    int rb_ = lane >> 2;
    int cb = wn * 64 + (lane & 3) * 2;
#pragma unroll
    for (int mt = 0; mt < 4; mt++)
#pragma unroll
        for (int nb = 0; nb < 8; nb++) {
            int col = cb + nb * 8;
            float bv0 = sbias[col], bv1 = sbias[col + 1];
#pragma unroll
            for (int h = 0; h < 2; h++) {
                int rloc = wm2 * 64 + mt * 16 + h * 8 + rb_;
                if (rloc < valid) {
                    float v0 = acc[mt][nb][h*2]   + bv0;
                    float v1 = acc[mt][nb][h*2+1] + bv1;
                    if (G1) {
                        v0 = v0 / (1.f + __expf(-v0));
                        v1 = v1 / (1.f + __expf(-v1));
                        size_t go = (size_t)(row0 + rloc) * (NH/2) + (n0 + col)/2;
                        g_HhW[go] = pack2(v0, v1);
                        g_HlW[go] = pack2lo(v0, v1);
                    } else {
                        size_t go = (size_t)(row0 + rloc) * ND + n0 + col;
                        *(float2*)&g_Y[go] = make_float2(v0, v1);
                    }
                }
            }
        }
}

// ---------------- combine ----------------------------------------------------
__global__ __launch_bounds__(256) void k_combine(float* __restrict__ out) {
    int idx = blockIdx.x * 256 + threadIdx.x;
    int t = idx >> 8;
    int c = (idx & 255) << 2;
    float w0 = g_topw[t*2], w1 = g_topw[t*2+1];
    int s0 = g_slot[t*2], s1 = g_slot[t*2+1];
    float4 y0 = *(const float4*)&g_Y[(size_t)s0 * ND + c];
    float4 y1 = *(const float4*)&g_Y[(size_t)s1 * ND + c];
    float4 o;
    o.x = w0*y0.x + w1*y1.x; o.y = w0*y0.y + w1*y1.y;
    o.z = w0*y0.z + w1*y1.z; o.w = w0*y0.w + w1*y1.w;
    *(float4*)&out[(size_t)t * ND + c] = o;
}

// ---------------- launch -----------------------------------------------------
extern "C" void kernel_launch(void* const* d_in, const int* in_sizes, int n_in,
                              void* d_out, int out_size) {
    const float* x  = (const float*)d_in[0];
    const float* Wg = (const float*)d_in[1];
    const float* W1 = (const float*)d_in[2];
    const float* b1 = (const float*)d_in[3];
    const float* W2 = (const float*)d_in[4];
    const float* b2 = (const float*)d_in[5];
    float* out = (float*)d_out;

    cudaFuncSetAttribute(k_gemm<ND, true>,  cudaFuncAttributeMaxDynamicSharedMemorySize, SMEM_DYN);
    cudaFuncSetAttribute(k_gemm<NH, false>, cudaFuncAttributeMaxDynamicSharedMemorySize, SMEM_DYN);

    k_init<<<1, 32>>>();
    k_router<<<NT / 8, 256>>>(x, Wg);
    k_scan<<<1, 32>>>(out, out_size);
    k_fill<<<NT / 256, 256>>>();
    k_gather<<<2 * NT * 128 / 256, 256>>>(x);
    k_split<ND, NH, true ><<<dim3((ND/2)*(NH/4)/256, NE), 256>>>(W1);
    k_split<NH, ND, false><<<dim3((NH/2)*(ND/4)/256, NE), 256>>>(W2);
    k_gemm<ND, true><<<dim3(64, NH / BN, NE), 256, SMEM_DYN>>>(b1);
    k_gemm<NH, false><<<dim3(64, ND / BN, NE), 256, SMEM_DYN>>>(b2);
    k_combine<<<NT * ND / 4 / 256, 256>>>(out);
}